// round 1
// baseline (speedup 1.0000x reference)
#include <cuda_runtime.h>
#include <cuda_bf16.h>
#include <mma.h>

using namespace nvcuda;

#define N_NODES 20000
#define BATCH   2
#define FIN     256
#define NE      320000
#define EDIM    64
#define NH      8
#define NC      32
#define HC      256
#define M_ROWS  (N_NODES * BATCH)   // 40000
#define NCOLS   1024                // Q|K|V|R

#define FULLMASK 0xffffffffu
__device__ __forceinline__ float neg_inf() { return __int_as_float(0xff800000); }

// ---------------- scratch (device globals: the sanctioned alloc-free path) ---
__device__ float g_qkvr[(size_t)M_ROWS * NCOLS];   // 163.8 MB
__device__ float g_ebias[NE * NH];                 // 10.2 MB
__device__ float g_logits[NE * BATCH * NH];        // 20.5 MB  (CSR-permuted order)
__device__ int   g_rowptr[N_NODES + 1];
__device__ int   g_cursor[N_NODES];
__device__ int   g_counts[N_NODES];
__device__ int   g_perm[NE];
__device__ float g_wesum[EDIM * NH];

// ---------------------------------------------------------------- CSR build --
__global__ void zero_counts_kernel() {
    int i = blockIdx.x * blockDim.x + threadIdx.x;
    if (i < N_NODES) g_counts[i] = 0;
}

__global__ void hist_kernel(const int* __restrict__ edst) {
    int i = blockIdx.x * blockDim.x + threadIdx.x;
    if (i < NE) atomicAdd(&g_counts[edst[i]], 1);
}

__global__ void scan_kernel() {
    __shared__ int sd[1024];
    const int CH = 20;                       // 1024*20 >= 20000
    int t = threadIdx.x;
    int base = t * CH;
    int local[CH];
    int s = 0;
#pragma unroll
    for (int i = 0; i < CH; i++) {
        int idx = base + i;
        int v = (idx < N_NODES) ? g_counts[idx] : 0;
        local[i] = v;
        s += v;
    }
    sd[t] = s;
    __syncthreads();
    for (int off = 1; off < 1024; off <<= 1) {
        int v = (t >= off) ? sd[t - off] : 0;
        __syncthreads();
        sd[t] += v;
        __syncthreads();
    }
    int run = sd[t] - s;                     // exclusive prefix
#pragma unroll
    for (int i = 0; i < CH; i++) {
        int idx = base + i;
        if (idx < N_NODES) {
            g_rowptr[idx] = run;
            g_cursor[idx] = run;
            run += local[i];
        }
    }
    if (t == 0) g_rowptr[N_NODES] = NE;
}

__global__ void scatter_kernel(const int* __restrict__ edst) {
    int i = blockIdx.x * blockDim.x + threadIdx.x;
    if (i < NE) {
        int d = edst[i];
        int pos = atomicAdd(&g_cursor[d], 1);
        g_perm[pos] = i;
    }
}

// ------------------------------------------------------------------- WeSum ---
// wesum[d][h] = sum_c We[d, h*32+c]   (collapses the edge-feature GEMM)
__global__ void wesum_kernel(const float* __restrict__ We) {
    int t = threadIdx.x;           // 512 = 64*8
    int d = t >> 3, h = t & 7;
    float s = 0.f;
#pragma unroll
    for (int c = 0; c < NC; c++) s += We[d * HC + h * NC + c];
    g_wesum[t] = s;
}

// ----------------------------------------------------------- ebias = E@WeSum -
__global__ void __launch_bounds__(256) ebias_kernel(const float* __restrict__ edata) {
    __shared__ float sE[32][65];
    __shared__ float sW[EDIM * NH];
    int t = threadIdx.x;
    int e0 = blockIdx.x * 32;
    // load 32x64 edata tile (512 float4)
#pragma unroll
    for (int r = 0; r < 2; r++) {
        int idx = t + r * 256;               // 0..511
        int row = idx >> 4;
        int c4 = idx & 15;
        float4 v = *(const float4*)(edata + (size_t)(e0 + row) * EDIM + c4 * 4);
        sE[row][c4 * 4 + 0] = v.x;
        sE[row][c4 * 4 + 1] = v.y;
        sE[row][c4 * 4 + 2] = v.z;
        sE[row][c4 * 4 + 3] = v.w;
    }
#pragma unroll
    for (int r = 0; r < 2; r++) {
        int idx = t + r * 256;
        sW[idx] = g_wesum[idx];
    }
    __syncthreads();
    int el = t >> 3, h = t & 7;
    float a = 0.f;
#pragma unroll
    for (int d = 0; d < EDIM; d++) a += sE[el][d] * sW[d * NH + h];
    g_ebias[(e0 + el) * NH + h] = a;
}

// ------------------------------------------------- fused QKVR GEMM (tf32 wmma)
__global__ void __launch_bounds__(256) gemm_qkvr_kernel(
    const float* __restrict__ X,
    const float* __restrict__ Wq, const float* __restrict__ bq,
    const float* __restrict__ Wk, const float* __restrict__ bk,
    const float* __restrict__ Wv, const float* __restrict__ bv,
    const float* __restrict__ Wr, const float* __restrict__ br)
{
    constexpr int BM = 128, BN = 64, BK = 32;
    __shared__ float smem[BM * BN];          // 8192 floats: A|B while looping, C in epilogue
    float* sA = smem;                        // BM*BK = 4096
    float* sB = smem + BM * BK;              // BK*BN = 2048

    const int tid = threadIdx.x;
    const int warp = tid >> 5;
    const int wm = warp >> 1;                // 0..3
    const int wn = warp & 1;                 // 0..1
    const int m0 = blockIdx.x * BM;
    const int n0 = blockIdx.y * BN;          // 0..1023
    const float* W; const float* bias;
    switch (n0 >> 8) {
        case 0:  W = Wq; bias = bq; break;
        case 1:  W = Wk; bias = bk; break;
        case 2:  W = Wv; bias = bv; break;
        default: W = Wr; bias = br; break;
    }
    const int wcol0 = n0 & 255;

    wmma::fragment<wmma::accumulator, 16, 16, 8, float> acc[2][2];
#pragma unroll
    for (int i = 0; i < 2; i++)
#pragma unroll
        for (int j = 0; j < 2; j++) wmma::fill_fragment(acc[i][j], 0.f);

    for (int k0 = 0; k0 < FIN; k0 += BK) {
        // A tile: 128x32 = 1024 float4 / 256 thr
#pragma unroll
        for (int r = 0; r < 4; r++) {
            int idx = tid + r * 256;
            int row = idx >> 3;
            int c4 = idx & 7;
            int gm = m0 + row;
            float4 v = make_float4(0.f, 0.f, 0.f, 0.f);
            if (gm < M_ROWS) v = *(const float4*)(X + (size_t)gm * FIN + k0 + c4 * 4);
            *(float4*)(sA + row * BK + c4 * 4) = v;
        }
        // B tile: 32x64 = 512 float4 / 256 thr
#pragma unroll
        for (int r = 0; r < 2; r++) {
            int idx = tid + r * 256;
            int row = idx >> 4;
            int c4 = idx & 15;
            float4 v = *(const float4*)(W + (size_t)(k0 + row) * HC + wcol0 + c4 * 4);
            *(float4*)(sB + row * BN + c4 * 4) = v;
        }
        __syncthreads();
#pragma unroll
        for (int ks = 0; ks < BK; ks += 8) {
            wmma::fragment<wmma::matrix_a, 16, 16, 8, wmma::precision::tf32, wmma::row_major> a[2];
            wmma::fragment<wmma::matrix_b, 16, 16, 8, wmma::precision::tf32, wmma::row_major> b[2];
#pragma unroll
            for (int i = 0; i < 2; i++) {
                wmma::load_matrix_sync(a[i], sA + (wm * 32 + i * 16) * BK + ks, BK);
#pragma unroll
                for (int tti = 0; tti < a[i].num_elements; tti++)
                    a[i].x[tti] = wmma::__float_to_tf32(a[i].x[tti]);
            }
#pragma unroll
            for (int j = 0; j < 2; j++) {
                wmma::load_matrix_sync(b[j], sB + ks * BN + wn * 32 + j * 16, BN);
#pragma unroll
                for (int ttj = 0; ttj < b[j].num_elements; ttj++)
                    b[j].x[ttj] = wmma::__float_to_tf32(b[j].x[ttj]);
            }
#pragma unroll
            for (int i = 0; i < 2; i++)
#pragma unroll
                for (int j = 0; j < 2; j++)
                    wmma::mma_sync(acc[i][j], a[i], b[j], acc[i][j]);
        }
        __syncthreads();
    }

    // epilogue through smem (coalesced stores + bias)
    float* sC = smem;
#pragma unroll
    for (int i = 0; i < 2; i++)
#pragma unroll
        for (int j = 0; j < 2; j++)
            wmma::store_matrix_sync(sC + (wm * 32 + i * 16) * BN + wn * 32 + j * 16,
                                    acc[i][j], BN, wmma::mem_row_major);
    __syncthreads();
#pragma unroll
    for (int r = 0; r < 8; r++) {
        int idx = tid + r * 256;            // float4 idx 0..2047
        int row = idx >> 4;
        int c4 = idx & 15;
        int gm = m0 + row;
        if (gm < M_ROWS) {
            float4 v = *(float4*)(sC + row * BN + c4 * 4);
            const float* bp = bias + wcol0 + c4 * 4;
            v.x += bp[0]; v.y += bp[1]; v.z += bp[2]; v.w += bp[3];
            *(float4*)(g_qkvr + (size_t)gm * NCOLS + n0 + c4 * 4) = v;
        }
    }
}

// -------------------------------------------------- per-edge logits (CSR ord.)
__global__ void __launch_bounds__(256) logits_kernel(
    const int* __restrict__ esrc, const int* __restrict__ edst)
{
    int w = blockIdx.x * 8 + (threadIdx.x >> 5);   // 0 .. NE*BATCH-1
    int lane = threadIdx.x & 31;
    int j = w >> 1;                                // CSR position
    int b = w & 1;
    int e = g_perm[j];
    int src = esrc[e];
    int dst = edst[e];
    const float* qrow = g_qkvr + (size_t)(dst * BATCH + b) * NCOLS;          // Q
    const float* krow = g_qkvr + (size_t)(src * BATCH + b) * NCOLS + 256;    // K
    float myl = 0.f;
#pragma unroll
    for (int h = 0; h < NH; h++) {
        float d = krow[h * NC + lane] * qrow[h * NC + lane];
#pragma unroll
        for (int o = 16; o; o >>= 1) d += __shfl_xor_sync(FULLMASK, d, o);
        if (lane == h) myl = d;
    }
    if (lane < NH) {
        const float scale = 0.17677669529663687f;  // 1/sqrt(32)
        g_logits[(j * BATCH + b) * NH + lane] = myl * scale + g_ebias[e * NH + lane];
    }
}

// ---------------------------------------- fused edge-softmax + aggregation ---
__global__ void __launch_bounds__(256) attn_kernel(
    const int* __restrict__ esrc, float* __restrict__ out)
{
    int w = blockIdx.x * 8 + (threadIdx.x >> 5);   // 0 .. N*B*H-1
    int lane = threadIdx.x & 31;
    int h = w & 7;
    int b = (w >> 3) & 1;
    int dst = w >> 4;

    int rp0 = g_rowptr[dst];
    int rp1 = g_rowptr[dst + 1];
    int deg = rp1 - rp0;
    int col = h * NC + lane;
    size_t row = (size_t)(dst * BATCH + b);
    float racc = g_qkvr[row * NCOLS + 768 + col];  // R term

    float acc = 0.f;
    if (deg > 0) {
        if (deg <= 32) {
            int j = rp0 + lane;
            bool act = j < rp1;
            int e = act ? g_perm[j] : 0;
            int src = act ? esrc[e] : 0;
            float l = act ? g_logits[(j * BATCH + b) * NH + h] : neg_inf();
            float m = l;
#pragma unroll
            for (int o = 16; o; o >>= 1) m = fmaxf(m, __shfl_xor_sync(FULLMASK, m, o));
            float p = act ? __expf(l - m) : 0.f;
            float z = p;
#pragma unroll
            for (int o = 16; o; o >>= 1) z += __shfl_xor_sync(FULLMASK, z, o);
            float invz = 1.f / z;
            for (int jj = 0; jj < deg; jj++) {
                float wgt = __shfl_sync(FULLMASK, p, jj);
                int s = __shfl_sync(FULLMASK, src, jj);
                acc += wgt * g_qkvr[(size_t)(s * BATCH + b) * NCOLS + 512 + col];
            }
            acc *= invz;
        } else {
            // chunked online softmax (rare: Poisson(16) tail)
            float m = neg_inf(), z = 0.f;
            for (int base = rp0; base < rp1; base += 32) {
                int j = base + lane;
                bool act = j < rp1;
                float l = act ? g_logits[(j * BATCH + b) * NH + h] : neg_inf();
                float cm = l;
#pragma unroll
                for (int o = 16; o; o >>= 1) cm = fmaxf(cm, __shfl_xor_sync(FULLMASK, cm, o));
                float p = act ? __expf(l - cm) : 0.f;
                float cz = p;
#pragma unroll
                for (int o = 16; o; o >>= 1) cz += __shfl_xor_sync(FULLMASK, cz, o);
                if (cm > m) { z = z * __expf(m - cm) + cz; m = cm; }
                else        { z += cz * __expf(cm - m); }
            }
            float invz = 1.f / z;
            for (int j = rp0; j < rp1; j++) {
                int e = g_perm[j];
                int s = esrc[e];
                float l = g_logits[(j * BATCH + b) * NH + h];
                acc += __expf(l - m) * g_qkvr[(size_t)(s * BATCH + b) * NCOLS + 512 + col];
            }
            acc *= invz;
        }
    }
    out[row * HC + col] = acc + racc;
}

// ------------------------------------------------------------------- launch --
extern "C" void kernel_launch(void* const* d_in, const int* in_sizes, int n_in,
                              void* d_out, int out_size) {
    const float* x     = (const float*)d_in[0];
    const float* edata = (const float*)d_in[1];
    const int*   esrc  = (const int*)d_in[2];
    const int*   edst  = (const int*)d_in[3];
    const float* Wq    = (const float*)d_in[4];
    const float* bq    = (const float*)d_in[5];
    const float* Wk    = (const float*)d_in[6];
    const float* bk    = (const float*)d_in[7];
    const float* Wv    = (const float*)d_in[8];
    const float* bv    = (const float*)d_in[9];
    const float* We    = (const float*)d_in[10];
    const float* Wr    = (const float*)d_in[11];
    const float* br    = (const float*)d_in[12];
    float* out = (float*)d_out;

    zero_counts_kernel<<<(N_NODES + 255) / 256, 256>>>();
    hist_kernel<<<(NE + 255) / 256, 256>>>(edst);
    scan_kernel<<<1, 1024>>>();
    scatter_kernel<<<(NE + 255) / 256, 256>>>(edst);
    wesum_kernel<<<1, 512>>>(We);

    dim3 ggrid((M_ROWS + 127) / 128, NCOLS / 64);
    gemm_qkvr_kernel<<<ggrid, 256>>>(x, Wq, bq, Wk, bk, Wv, bv, Wr, br);

    ebias_kernel<<<NE / 32, 256>>>(edata);
    logits_kernel<<<NE * BATCH / 8, 256>>>(esrc, edst);
    attn_kernel<<<N_NODES * BATCH * NH / 8, 256>>>(esrc, out);
}

// round 5
// speedup vs baseline: 1.2625x; 1.2625x over previous
#include <cstdint>
#include <cuda_runtime.h>
#include <cuda_bf16.h>
#include <mma.h>

using namespace nvcuda;

#define N_NODES 20000
#define BATCH   2
#define FIN     256
#define NE      320000
#define EDIM    64
#define NH      8
#define NC      32
#define HC      256
#define M_ROWS  (N_NODES * BATCH)   // 40000
#define NCOLS   1024                // Q|K|V|R

#define FULLMASK 0xffffffffu
__device__ __forceinline__ float neg_inf() { return __int_as_float(0xff800000); }

// ---------------- scratch (device globals: the sanctioned alloc-free path) ---
__device__ float g_qkvr[(size_t)M_ROWS * NCOLS];   // 163.8 MB
__device__ float g_ebias[NE * NH];                 // 10.2 MB
__device__ float g_logits[NE * BATCH * NH];        // 20.5 MB  (CSR-permuted order)
__device__ int   g_rowptr[N_NODES + 1];
__device__ int   g_cursor[N_NODES];
__device__ int   g_counts[N_NODES];
__device__ int   g_perm[NE];
__device__ float g_wesum[EDIM * NH];

// ----------------------------------------------------------- cp.async helpers
__device__ __forceinline__ void cp_async16(void* sptr, const void* gptr, bool pred) {
    unsigned int saddr = (unsigned int)__cvta_generic_to_shared(sptr);
    int sz = pred ? 16 : 0;
    asm volatile("cp.async.cg.shared.global [%0], [%1], 16, %2;\n"
                 :: "r"(saddr), "l"(gptr), "r"(sz));
}
__device__ __forceinline__ void cp_commit() { asm volatile("cp.async.commit_group;\n"); }
template<int Nn>
__device__ __forceinline__ void cp_wait() { asm volatile("cp.async.wait_group %0;\n" :: "n"(Nn)); }

// ---------------------------------------------------------------- CSR build --
__global__ void zero_counts_kernel() {
    int i = blockIdx.x * blockDim.x + threadIdx.x;
    if (i < N_NODES) g_counts[i] = 0;
}

__global__ void hist_kernel(const int* __restrict__ edst) {
    int i = blockIdx.x * blockDim.x + threadIdx.x;
    if (i < NE) atomicAdd(&g_counts[edst[i]], 1);
}

__global__ void scan_kernel() {
    __shared__ int sd[1024];
    const int CH = 20;                       // 1024*20 >= 20000
    int t = threadIdx.x;
    int base = t * CH;
    int local[CH];
    int s = 0;
#pragma unroll
    for (int i = 0; i < CH; i++) {
        int idx = base + i;
        int v = (idx < N_NODES) ? g_counts[idx] : 0;
        local[i] = v;
        s += v;
    }
    sd[t] = s;
    __syncthreads();
    for (int off = 1; off < 1024; off <<= 1) {
        int v = (t >= off) ? sd[t - off] : 0;
        __syncthreads();
        sd[t] += v;
        __syncthreads();
    }
    int run = sd[t] - s;                     // exclusive prefix
#pragma unroll
    for (int i = 0; i < CH; i++) {
        int idx = base + i;
        if (idx < N_NODES) {
            g_rowptr[idx] = run;
            g_cursor[idx] = run;
            run += local[i];
        }
    }
    if (t == 0) g_rowptr[N_NODES] = NE;
}

__global__ void scatter_kernel(const int* __restrict__ edst) {
    int i = blockIdx.x * blockDim.x + threadIdx.x;
    if (i < NE) {
        int d = edst[i];
        int pos = atomicAdd(&g_cursor[d], 1);
        g_perm[pos] = i;
    }
}

// ------------------------------------------------------------------- WeSum ---
__global__ void wesum_kernel(const float* __restrict__ We) {
    int t = threadIdx.x;           // 512 = 64*8
    int d = t >> 3, h = t & 7;
    float s = 0.f;
#pragma unroll
    for (int c = 0; c < NC; c++) s += We[d * HC + h * NC + c];
    g_wesum[t] = s;
}

// ----------------------------------------------------------- ebias = E@WeSum -
__global__ void __launch_bounds__(256) ebias_kernel(const float* __restrict__ edata) {
    __shared__ float sE[32][65];
    __shared__ float sW[EDIM * NH];
    int t = threadIdx.x;
    int e0 = blockIdx.x * 32;
#pragma unroll
    for (int r = 0; r < 2; r++) {
        int idx = t + r * 256;               // 0..511
        int row = idx >> 4;
        int c4 = idx & 15;
        float4 v = *(const float4*)(edata + (size_t)(e0 + row) * EDIM + c4 * 4);
        sE[row][c4 * 4 + 0] = v.x;
        sE[row][c4 * 4 + 1] = v.y;
        sE[row][c4 * 4 + 2] = v.z;
        sE[row][c4 * 4 + 3] = v.w;
    }
#pragma unroll
    for (int r = 0; r < 2; r++) {
        int idx = t + r * 256;
        sW[idx] = g_wesum[idx];
    }
    __syncthreads();
    int el = t >> 3, h = t & 7;
    float a = 0.f;
#pragma unroll
    for (int d = 0; d < EDIM; d++) a += sE[el][d] * sW[d * NH + h];
    g_ebias[(e0 + el) * NH + h] = a;
}

// ------------------------------------- fused QKVR GEMM (tf32 wmma, 3-stage) --
#define BM 128
#define BN 128
#define BKK 32
#define STAGES 3
#define STAGE_FLOATS (BM * BKK + BKK * BN)   // 8192 floats = 32KB

__global__ void __launch_bounds__(256) gemm_qkvr_kernel(
    const float* __restrict__ X,
    const float* __restrict__ Wq, const float* __restrict__ bq,
    const float* __restrict__ Wk, const float* __restrict__ bk,
    const float* __restrict__ Wv, const float* __restrict__ bv,
    const float* __restrict__ Wr, const float* __restrict__ br)
{
    extern __shared__ float smem[];

    const int tid  = threadIdx.x;
    const int warp = tid >> 5;
    const int wm   = warp >> 1;              // 0..3 (32 rows each)
    const int wn   = warp & 1;               // 0..1 (64 cols each)
    const int m0   = blockIdx.x * BM;
    const int n0   = blockIdx.y * BN;        // 0,128,...,896
    const float* W; const float* bias;
    switch (n0 >> 8) {
        case 0:  W = Wq; bias = bq; break;
        case 1:  W = Wk; bias = bk; break;
        case 2:  W = Wv; bias = bv; break;
        default: W = Wr; bias = br; break;
    }
    const int wcol0 = n0 & 255;

    auto load_stage = [&](int s, int k0) {
        float* sA = smem + s * STAGE_FLOATS;
        float* sB = sA + BM * BKK;
#pragma unroll
        for (int r = 0; r < 4; r++) {        // A: 128x32 = 1024 float4
            int idx = tid + r * 256;
            int row = idx >> 3, c4 = idx & 7;
            int gm = m0 + row;
            bool ok = gm < M_ROWS;
            int gms = ok ? gm : (M_ROWS - 1);
            cp_async16(sA + row * BKK + c4 * 4,
                       X + (size_t)gms * FIN + k0 + c4 * 4, ok);
        }
#pragma unroll
        for (int r = 0; r < 4; r++) {        // B: 32x128 = 1024 float4
            int idx = tid + r * 256;
            int row = idx >> 5, c4 = idx & 31;
            cp_async16(sB + row * BN + c4 * 4,
                       W + (size_t)(k0 + row) * HC + wcol0 + c4 * 4, true);
        }
        cp_commit();
    };

    wmma::fragment<wmma::accumulator, 16, 16, 8, float> acc[2][4];
#pragma unroll
    for (int i = 0; i < 2; i++)
#pragma unroll
        for (int j = 0; j < 4; j++) wmma::fill_fragment(acc[i][j], 0.f);

    load_stage(0, 0);
    load_stage(1, BKK);

    const int KT = FIN / BKK;                // 8
    for (int kt = 0; kt < KT; kt++) {
        if (kt == KT - 1) cp_wait<0>(); else cp_wait<1>();
        __syncthreads();
        // issue next stage early (overlap with compute)
        int knext = (kt + STAGES - 1) * BKK;
        if (knext < FIN) load_stage((kt + STAGES - 1) % STAGES, knext);

        float* sA = smem + (kt % STAGES) * STAGE_FLOATS;
        float* sB = sA + BM * BKK;
#pragma unroll
        for (int ks = 0; ks < BKK; ks += 8) {
            wmma::fragment<wmma::matrix_a, 16, 16, 8, wmma::precision::tf32, wmma::row_major> a[2];
            wmma::fragment<wmma::matrix_b, 16, 16, 8, wmma::precision::tf32, wmma::row_major> b[4];
#pragma unroll
            for (int i = 0; i < 2; i++) {
                wmma::load_matrix_sync(a[i], sA + (wm * 32 + i * 16) * BKK + ks, BKK);
#pragma unroll
                for (int tt = 0; tt < a[i].num_elements; tt++)
                    a[i].x[tt] = wmma::__float_to_tf32(a[i].x[tt]);
            }
#pragma unroll
            for (int j = 0; j < 4; j++) {
                wmma::load_matrix_sync(b[j], sB + ks * BN + wn * 64 + j * 16, BN);
#pragma unroll
                for (int tt = 0; tt < b[j].num_elements; tt++)
                    b[j].x[tt] = wmma::__float_to_tf32(b[j].x[tt]);
            }
#pragma unroll
            for (int i = 0; i < 2; i++)
#pragma unroll
                for (int j = 0; j < 4; j++)
                    wmma::mma_sync(acc[i][j], a[i], b[j], acc[i][j]);
        }
        __syncthreads();
    }

    // epilogue: stage C through smem (64KB), coalesced fp32 stores + bias
    float* sC = smem;
#pragma unroll
    for (int i = 0; i < 2; i++)
#pragma unroll
        for (int j = 0; j < 4; j++)
            wmma::store_matrix_sync(sC + (wm * 32 + i * 16) * BN + wn * 64 + j * 16,
                                    acc[i][j], BN, wmma::mem_row_major);
    __syncthreads();
#pragma unroll
    for (int r = 0; r < 16; r++) {
        int idx = tid + r * 256;             // 0..4095 float4
        int row = idx >> 5;
        int c4 = idx & 31;
        int gm = m0 + row;
        if (gm < M_ROWS) {
            float4 v = *(float4*)(sC + row * BN + c4 * 4);
            const float* bp = bias + wcol0 + c4 * 4;
            v.x += bp[0]; v.y += bp[1]; v.z += bp[2]; v.w += bp[3];
            *(float4*)(g_qkvr + (size_t)gm * NCOLS + n0 + c4 * 4) = v;
        }
    }
}

// ----------------------------- per-edge logits: warp per (dst, b), CSR order -
// lane l owns q/k floats [l*8, l*8+8): head h = l>>2, quad-butterfly reduce.
__global__ void __launch_bounds__(256) logits_kernel(const int* __restrict__ esrc)
{
    int w = blockIdx.x * 8 + (threadIdx.x >> 5);   // 0 .. N*B-1
    int lane = threadIdx.x & 31;
    int b = w & 1;
    int dst = w >> 1;

    int rp0 = g_rowptr[dst];
    int rp1 = g_rowptr[dst + 1];
    if (rp0 == rp1) return;

    const float* qrow = g_qkvr + (size_t)(dst * BATCH + b) * NCOLS;  // Q
    float4 q0 = *(const float4*)(qrow + lane * 8);
    float4 q1 = *(const float4*)(qrow + lane * 8 + 4);
    int h = lane >> 2;
    const float scale = 0.17677669529663687f;      // 1/sqrt(32)

    for (int base = rp0; base < rp1; base += 32) {
        int j = base + lane;
        bool act = j < rp1;
        int e   = act ? g_perm[j] : 0;
        int src = act ? esrc[e] : 0;
        int cnt = min(32, rp1 - base);
        for (int jj = 0; jj < cnt; jj++) {
            int s  = __shfl_sync(FULLMASK, src, jj);
            int ee = __shfl_sync(FULLMASK, e, jj);
            const float* krow = g_qkvr + (size_t)(s * BATCH + b) * NCOLS + 256;
            float4 k0 = *(const float4*)(krow + lane * 8);
            float4 k1 = *(const float4*)(krow + lane * 8 + 4);
            float d = q0.x * k0.x + q0.y * k0.y + q0.z * k0.z + q0.w * k0.w
                    + q1.x * k1.x + q1.y * k1.y + q1.z * k1.z + q1.w * k1.w;
            d += __shfl_xor_sync(FULLMASK, d, 1);
            d += __shfl_xor_sync(FULLMASK, d, 2);
            if ((lane & 3) == 0)
                g_logits[((base + jj) * BATCH + b) * NH + h] =
                    d * scale + g_ebias[ee * NH + h];
        }
    }
}

// ---------------------------------------- fused edge-softmax + aggregation ---
__global__ void __launch_bounds__(256) attn_kernel(
    const int* __restrict__ esrc, float* __restrict__ out)
{
    int w = blockIdx.x * 8 + (threadIdx.x >> 5);   // 0 .. N*B*H-1
    int lane = threadIdx.x & 31;
    int h = w & 7;
    int b = (w >> 3) & 1;
    int dst = w >> 4;

    int rp0 = g_rowptr[dst];
    int rp1 = g_rowptr[dst + 1];
    int deg = rp1 - rp0;
    int col = h * NC + lane;
    size_t row = (size_t)(dst * BATCH + b);
    float racc = g_qkvr[row * NCOLS + 768 + col];  // R term

    float acc = 0.f;
    if (deg > 0) {
        if (deg <= 32) {
            int j = rp0 + lane;
            bool act = j < rp1;
            int e = act ? g_perm[j] : 0;
            int src = act ? esrc[e] : 0;
            float l = act ? g_logits[(j * BATCH + b) * NH + h] : neg_inf();
            float m = l;
#pragma unroll
            for (int o = 16; o; o >>= 1) m = fmaxf(m, __shfl_xor_sync(FULLMASK, m, o));
            float p = act ? __expf(l - m) : 0.f;
            float z = p;
#pragma unroll
            for (int o = 16; o; o >>= 1) z += __shfl_xor_sync(FULLMASK, z, o);
            float invz = 1.f / z;
            for (int jj = 0; jj < deg; jj++) {
                float wgt = __shfl_sync(FULLMASK, p, jj);
                int s = __shfl_sync(FULLMASK, src, jj);
                acc += wgt * g_qkvr[(size_t)(s * BATCH + b) * NCOLS + 512 + col];
            }
            acc *= invz;
        } else {
            float m = neg_inf(), z = 0.f;
            for (int base = rp0; base < rp1; base += 32) {
                int j = base + lane;
                bool act = j < rp1;
                float l = act ? g_logits[(j * BATCH + b) * NH + h] : neg_inf();
                float cm = l;
#pragma unroll
                for (int o = 16; o; o >>= 1) cm = fmaxf(cm, __shfl_xor_sync(FULLMASK, cm, o));
                float p = act ? __expf(l - cm) : 0.f;
                float cz = p;
#pragma unroll
                for (int o = 16; o; o >>= 1) cz += __shfl_xor_sync(FULLMASK, cz, o);
                if (cm > m) { z = z * __expf(m - cm) + cz; m = cm; }
                else        { z += cz * __expf(cm - m); }
            }
            float invz = 1.f / z;
            for (int j = rp0; j < rp1; j++) {
                int e = g_perm[j];
                int s = esrc[e];
                float l = g_logits[(j * BATCH + b) * NH + h];
                acc += __expf(l - m) * g_qkvr[(size_t)(s * BATCH + b) * NCOLS + 512 + col];
            }
            acc *= invz;
        }
    }
    out[row * HC + col] = acc + racc;
}

// ------------------------------------------------------------------- launch --
extern "C" void kernel_launch(void* const* d_in, const int* in_sizes, int n_in,
                              void* d_out, int out_size) {
    const float* x     = (const float*)d_in[0];
    const float* edata = (const float*)d_in[1];
    const int*   esrc  = (const int*)d_in[2];
    const int*   edst  = (const int*)d_in[3];
    const float* Wq    = (const float*)d_in[4];
    const float* bq    = (const float*)d_in[5];
    const float* Wk    = (const float*)d_in[6];
    const float* bk    = (const float*)d_in[7];
    const float* Wv    = (const float*)d_in[8];
    const float* bv    = (const float*)d_in[9];
    const float* We    = (const float*)d_in[10];
    const float* Wr    = (const float*)d_in[11];
    const float* br    = (const float*)d_in[12];
    float* out = (float*)d_out;

    static bool attr_set = false;
    if (!attr_set) {
        cudaFuncSetAttribute(gemm_qkvr_kernel,
                             cudaFuncAttributeMaxDynamicSharedMemorySize,
                             STAGES * STAGE_FLOATS * 4);
        attr_set = true;
    }

    // order: harness memset x2 precede; gemm is 4th here -> ncu -s5 captures it
    zero_counts_kernel<<<(N_NODES + 255) / 256, 256>>>();
    hist_kernel<<<(NE + 255) / 256, 256>>>(edst);
    scan_kernel<<<1, 1024>>>();

    dim3 ggrid((M_ROWS + BM - 1) / BM, NCOLS / BN);
    gemm_qkvr_kernel<<<ggrid, 256, STAGES * STAGE_FLOATS * 4>>>(
        x, Wq, bq, Wk, bk, Wv, bv, Wr, br);

    scatter_kernel<<<(NE + 255) / 256, 256>>>(edst);
    wesum_kernel<<<1, 512>>>(We);
    ebias_kernel<<<NE / 32, 256>>>(edata);
    logits_kernel<<<N_NODES * BATCH / 8, 256>>>(esrc);
    attn_kernel<<<N_NODES * BATCH * NH / 8, 256>>>(esrc, out);
}

// round 7
// speedup vs baseline: 1.5626x; 1.2377x over previous
#include <cstdint>
#include <cuda_runtime.h>
#include <cuda_bf16.h>
#include <mma.h>

using namespace nvcuda;

#define N_NODES 20000
#define BATCH   2
#define FIN     256
#define NE      320000
#define EDIM    64
#define NH      8
#define NC      32
#define HC      256
#define M_ROWS  (N_NODES * BATCH)   // 40000
#define NCOLS   1024                // Q|K|V|R

#define FULLMASK 0xffffffffu
__device__ __forceinline__ float neg_inf() { return __int_as_float(0xff800000); }

// ---------------- scratch (device globals: the sanctioned alloc-free path) ---
__device__ float g_qkvr[(size_t)M_ROWS * NCOLS];   // 163.8 MB
__device__ float g_ebias[NE * NH];                 // 10.2 MB
__device__ float g_logits[NE * BATCH * NH];        // 20.5 MB  (CSR-permuted order)
__device__ int   g_rowptr[N_NODES + 1];
__device__ int   g_cursor[N_NODES];
__device__ int   g_counts[N_NODES];
__device__ int   g_perm[NE];
__device__ float g_wesum[EDIM * NH];

// ----------------------------------------------------------- cp.async helpers
__device__ __forceinline__ void cp_async16(void* sptr, const void* gptr, bool pred) {
    unsigned int saddr = (unsigned int)__cvta_generic_to_shared(sptr);
    int sz = pred ? 16 : 0;
    asm volatile("cp.async.cg.shared.global [%0], [%1], 16, %2;\n"
                 :: "r"(saddr), "l"(gptr), "r"(sz));
}
__device__ __forceinline__ void cp_commit() { asm volatile("cp.async.commit_group;\n"); }
template<int Nn>
__device__ __forceinline__ void cp_wait() { asm volatile("cp.async.wait_group %0;\n" :: "n"(Nn)); }

// ---------------------------------------------------------------- CSR build --
__global__ void zero_counts_kernel() {
    int i = blockIdx.x * blockDim.x + threadIdx.x;
    if (i < N_NODES) g_counts[i] = 0;
}

__global__ void hist_kernel(const int* __restrict__ edst) {
    int i = blockIdx.x * blockDim.x + threadIdx.x;
    if (i < NE) atomicAdd(&g_counts[edst[i]], 1);
}

__global__ void scan_kernel() {
    __shared__ int sd[1024];
    const int CH = 20;                       // 1024*20 >= 20000
    int t = threadIdx.x;
    int base = t * CH;
    int local[CH];
    int s = 0;
#pragma unroll
    for (int i = 0; i < CH; i++) {
        int idx = base + i;
        int v = (idx < N_NODES) ? g_counts[idx] : 0;
        local[i] = v;
        s += v;
    }
    sd[t] = s;
    __syncthreads();
    for (int off = 1; off < 1024; off <<= 1) {
        int v = (t >= off) ? sd[t - off] : 0;
        __syncthreads();
        sd[t] += v;
        __syncthreads();
    }
    int run = sd[t] - s;                     // exclusive prefix
#pragma unroll
    for (int i = 0; i < CH; i++) {
        int idx = base + i;
        if (idx < N_NODES) {
            g_rowptr[idx] = run;
            g_cursor[idx] = run;
            run += local[i];
        }
    }
    if (t == 0) g_rowptr[N_NODES] = NE;
}

__global__ void scatter_kernel(const int* __restrict__ edst) {
    int i = blockIdx.x * blockDim.x + threadIdx.x;
    if (i < NE) {
        int d = edst[i];
        int pos = atomicAdd(&g_cursor[d], 1);
        g_perm[pos] = i;
    }
}

// ------------------------------------------------------------------- WeSum ---
__global__ void wesum_kernel(const float* __restrict__ We) {
    int t = threadIdx.x;           // 512 = 64*8
    int d = t >> 3, h = t & 7;
    float s = 0.f;
#pragma unroll
    for (int c = 0; c < NC; c++) s += We[d * HC + h * NC + c];
    g_wesum[t] = s;
}

// ----------------------------------------------------------- ebias = E@WeSum -
__global__ void __launch_bounds__(256) ebias_kernel(const float* __restrict__ edata) {
    __shared__ float sE[32][65];
    __shared__ float sW[EDIM * NH];
    int t = threadIdx.x;
    int e0 = blockIdx.x * 32;
#pragma unroll
    for (int r = 0; r < 2; r++) {
        int idx = t + r * 256;               // 0..511
        int row = idx >> 4;
        int c4 = idx & 15;
        float4 v = *(const float4*)(edata + (size_t)(e0 + row) * EDIM + c4 * 4);
        sE[row][c4 * 4 + 0] = v.x;
        sE[row][c4 * 4 + 1] = v.y;
        sE[row][c4 * 4 + 2] = v.z;
        sE[row][c4 * 4 + 3] = v.w;
    }
#pragma unroll
    for (int r = 0; r < 2; r++) {
        int idx = t + r * 256;
        sW[idx] = g_wesum[idx];
    }
    __syncthreads();
    int el = t >> 3, h = t & 7;
    float a = 0.f;
#pragma unroll
    for (int d = 0; d < EDIM; d++) a += sE[el][d] * sW[d * NH + h];
    g_ebias[(e0 + el) * NH + h] = a;
}

// ---------------- fused QKVR GEMM (tf32 wmma, 64x64 warp tiles, 3-stage) -----
#define BM 128
#define BN 256
#define BKK 32
#define STAGES 3
#define PA 36                                 // padded A row stride (floats)
#define PB 264                                // padded B row stride (floats)
#define STAGE_FLOATS (BM * PA + BKK * PB)     // 4608 + 8448 = 13056 fl = 52.2KB
#define GEMM_SMEM (STAGES * STAGE_FLOATS * 4) // 156,672 B

__global__ void __launch_bounds__(256, 1) gemm_qkvr_kernel(
    const float* __restrict__ X,
    const float* __restrict__ Wq, const float* __restrict__ bq,
    const float* __restrict__ Wk, const float* __restrict__ bk,
    const float* __restrict__ Wv, const float* __restrict__ bv,
    const float* __restrict__ Wr, const float* __restrict__ br)
{
    extern __shared__ float smem[];

    const int tid  = threadIdx.x;
    const int warp = tid >> 5;
    const int wm   = warp >> 2;              // 0..1 (64 rows each)
    const int wn   = warp & 3;               // 0..3 (64 cols each)
    const int m0   = blockIdx.x * BM;
    const float* W; const float* bias;
    switch (blockIdx.y) {                    // one weight matrix per y-block
        case 0:  W = Wq; bias = bq; break;
        case 1:  W = Wk; bias = bk; break;
        case 2:  W = Wv; bias = bv; break;
        default: W = Wr; bias = br; break;
    }
    const int n0 = blockIdx.y * BN;

    auto load_stage = [&](int s, int k0) {
        float* sA = smem + s * STAGE_FLOATS;
        float* sB = sA + BM * PA;
#pragma unroll
        for (int r = 0; r < 4; r++) {        // A: 128x32 = 1024 float4
            int idx = tid + r * 256;
            int row = idx >> 3, c4 = idx & 7;
            int gm = m0 + row;
            bool ok = gm < M_ROWS;
            int gms = ok ? gm : (M_ROWS - 1);
            cp_async16(sA + row * PA + c4 * 4,
                       X + (size_t)gms * FIN + k0 + c4 * 4, ok);
        }
#pragma unroll
        for (int r = 0; r < 8; r++) {        // B: 32x256 = 2048 float4
            int idx = tid + r * 256;
            int row = idx >> 6, c4 = idx & 63;
            cp_async16(sB + row * PB + c4 * 4,
                       W + (size_t)(k0 + row) * HC + c4 * 4, true);
        }
        cp_commit();
    };

    wmma::fragment<wmma::accumulator, 16, 16, 8, float> acc[4][4];
#pragma unroll
    for (int i = 0; i < 4; i++)
#pragma unroll
        for (int j = 0; j < 4; j++) wmma::fill_fragment(acc[i][j], 0.f);

    load_stage(0, 0);
    load_stage(1, BKK);

    const int KT = FIN / BKK;                // 8
    for (int kt = 0; kt < KT; kt++) {
        if (kt == KT - 1) cp_wait<0>(); else cp_wait<1>();
        __syncthreads();
        int knext = (kt + STAGES - 1) * BKK;
        if (knext < FIN) load_stage((kt + STAGES - 1) % STAGES, knext);

        float* sA = smem + (kt % STAGES) * STAGE_FLOATS;
        float* sB = sA + BM * PA;
#pragma unroll
        for (int ks = 0; ks < BKK; ks += 8) {
            wmma::fragment<wmma::matrix_a, 16, 16, 8, wmma::precision::tf32, wmma::row_major> a[4];
            wmma::fragment<wmma::matrix_b, 16, 16, 8, wmma::precision::tf32, wmma::row_major> b[4];
#pragma unroll
            for (int i = 0; i < 4; i++)
                wmma::load_matrix_sync(a[i], sA + (wm * 64 + i * 16) * PA + ks, PA);
#pragma unroll
            for (int j = 0; j < 4; j++)
                wmma::load_matrix_sync(b[j], sB + ks * PB + wn * 64 + j * 16, PB);
            // no explicit __float_to_tf32: HMMA reads tf32 bits (truncation),
            // error still ~2^-10 per product, well under the 1e-3 gate.
#pragma unroll
            for (int i = 0; i < 4; i++)
#pragma unroll
                for (int j = 0; j < 4; j++)
                    wmma::mma_sync(acc[i][j], a[i], b[j], acc[i][j]);
        }
        __syncthreads();
    }

    // epilogue: stage 128x256 C through smem (stride PB), bias + coalesced out
    float* sC = smem;
#pragma unroll
    for (int i = 0; i < 4; i++)
#pragma unroll
        for (int j = 0; j < 4; j++)
            wmma::store_matrix_sync(sC + (wm * 64 + i * 16) * PB + wn * 64 + j * 16,
                                    acc[i][j], PB, wmma::mem_row_major);
    __syncthreads();
#pragma unroll
    for (int r = 0; r < 32; r++) {
        int idx = tid + r * 256;             // 0..8191 float4
        int row = idx >> 6;
        int c4 = idx & 63;
        int gm = m0 + row;
        if (gm < M_ROWS) {
            float4 v = *(float4*)(sC + row * PB + c4 * 4);
            const float* bp = bias + c4 * 4;
            v.x += bp[0]; v.y += bp[1]; v.z += bp[2]; v.w += bp[3];
            *(float4*)(g_qkvr + (size_t)gm * NCOLS + n0 + c4 * 4) = v;
        }
    }
}

// ----------------------------- per-edge logits: warp per (dst, b), CSR order -
// lane l owns q/k floats [l*8, l*8+8): head h = l>>2, quad-butterfly reduce.
__global__ void __launch_bounds__(256) logits_kernel(const int* __restrict__ esrc)
{
    int w = blockIdx.x * 8 + (threadIdx.x >> 5);   // 0 .. N*B-1
    int lane = threadIdx.x & 31;
    int b = w & 1;
    int dst = w >> 1;

    int rp0 = g_rowptr[dst];
    int rp1 = g_rowptr[dst + 1];
    if (rp0 == rp1) return;

    const float* qrow = g_qkvr + (size_t)(dst * BATCH + b) * NCOLS;  // Q
    float4 q0 = *(const float4*)(qrow + lane * 8);
    float4 q1 = *(const float4*)(qrow + lane * 8 + 4);
    int h = lane >> 2;
    const float scale = 0.17677669529663687f;      // 1/sqrt(32)

    for (int base = rp0; base < rp1; base += 32) {
        int j = base + lane;
        bool act = j < rp1;
        int e   = act ? g_perm[j] : 0;
        int src = act ? esrc[e] : 0;
        int cnt = min(32, rp1 - base);
        for (int jj = 0; jj < cnt; jj++) {
            int s  = __shfl_sync(FULLMASK, src, jj);
            int ee = __shfl_sync(FULLMASK, e, jj);
            const float* krow = g_qkvr + (size_t)(s * BATCH + b) * NCOLS + 256;
            float4 k0 = *(const float4*)(krow + lane * 8);
            float4 k1 = *(const float4*)(krow + lane * 8 + 4);
            float d = q0.x * k0.x + q0.y * k0.y + q0.z * k0.z + q0.w * k0.w
                    + q1.x * k1.x + q1.y * k1.y + q1.z * k1.z + q1.w * k1.w;
            d += __shfl_xor_sync(FULLMASK, d, 1);
            d += __shfl_xor_sync(FULLMASK, d, 2);
            if ((lane & 3) == 0)
                g_logits[((base + jj) * BATCH + b) * NH + h] =
                    d * scale + g_ebias[ee * NH + h];
        }
    }
}

// ---------------------------------------- fused edge-softmax + aggregation ---
__global__ void __launch_bounds__(256) attn_kernel(
    const int* __restrict__ esrc, float* __restrict__ out)
{
    int w = blockIdx.x * 8 + (threadIdx.x >> 5);   // 0 .. N*B*H-1
    int lane = threadIdx.x & 31;
    int h = w & 7;
    int b = (w >> 3) & 1;
    int dst = w >> 4;

    int rp0 = g_rowptr[dst];
    int rp1 = g_rowptr[dst + 1];
    int deg = rp1 - rp0;
    int col = h * NC + lane;
    size_t row = (size_t)(dst * BATCH + b);
    float racc = g_qkvr[row * NCOLS + 768 + col];  // R term

    float acc = 0.f;
    if (deg > 0) {
        if (deg <= 32) {
            int j = rp0 + lane;
            bool act = j < rp1;
            int e = act ? g_perm[j] : 0;
            int src = act ? esrc[e] : 0;
            float l = act ? g_logits[(j * BATCH + b) * NH + h] : neg_inf();
            float m = l;
#pragma unroll
            for (int o = 16; o; o >>= 1) m = fmaxf(m, __shfl_xor_sync(FULLMASK, m, o));
            float p = act ? __expf(l - m) : 0.f;
            float z = p;
#pragma unroll
            for (int o = 16; o; o >>= 1) z += __shfl_xor_sync(FULLMASK, z, o);
            float invz = 1.f / z;
            for (int jj = 0; jj < deg; jj++) {
                float wgt = __shfl_sync(FULLMASK, p, jj);
                int s = __shfl_sync(FULLMASK, src, jj);
                acc += wgt * g_qkvr[(size_t)(s * BATCH + b) * NCOLS + 512 + col];
            }
            acc *= invz;
        } else {
            float m = neg_inf(), z = 0.f;
            for (int base = rp0; base < rp1; base += 32) {
                int j = base + lane;
                bool act = j < rp1;
                float l = act ? g_logits[(j * BATCH + b) * NH + h] : neg_inf();
                float cm = l;
#pragma unroll
                for (int o = 16; o; o >>= 1) cm = fmaxf(cm, __shfl_xor_sync(FULLMASK, cm, o));
                float p = act ? __expf(l - cm) : 0.f;
                float cz = p;
#pragma unroll
                for (int o = 16; o; o >>= 1) cz += __shfl_xor_sync(FULLMASK, cz, o);
                if (cm > m) { z = z * __expf(m - cm) + cz; m = cm; }
                else        { z += cz * __expf(cm - m); }
            }
            float invz = 1.f / z;
            for (int j = rp0; j < rp1; j++) {
                int e = g_perm[j];
                int s = esrc[e];
                float l = g_logits[(j * BATCH + b) * NH + h];
                acc += __expf(l - m) * g_qkvr[(size_t)(s * BATCH + b) * NCOLS + 512 + col];
            }
            acc *= invz;
        }
    }
    out[row * HC + col] = acc + racc;
}

// ------------------------------------------------------------------- launch --
extern "C" void kernel_launch(void* const* d_in, const int* in_sizes, int n_in,
                              void* d_out, int out_size) {
    const float* x     = (const float*)d_in[0];
    const float* edata = (const float*)d_in[1];
    const int*   esrc  = (const int*)d_in[2];
    const int*   edst  = (const int*)d_in[3];
    const float* Wq    = (const float*)d_in[4];
    const float* bq    = (const float*)d_in[5];
    const float* Wk    = (const float*)d_in[6];
    const float* bk    = (const float*)d_in[7];
    const float* Wv    = (const float*)d_in[8];
    const float* bv    = (const float*)d_in[9];
    const float* We    = (const float*)d_in[10];
    const float* Wr    = (const float*)d_in[11];
    const float* br    = (const float*)d_in[12];
    float* out = (float*)d_out;

    static bool attr_set = false;
    if (!attr_set) {
        cudaFuncSetAttribute(gemm_qkvr_kernel,
                             cudaFuncAttributeMaxDynamicSharedMemorySize,
                             GEMM_SMEM);
        attr_set = true;
    }

    // order: harness memset x2 precede; gemm is 4th here -> ncu -s5 captures it
    zero_counts_kernel<<<(N_NODES + 255) / 256, 256>>>();
    hist_kernel<<<(NE + 255) / 256, 256>>>(edst);
    scan_kernel<<<1, 1024>>>();

    dim3 ggrid((M_ROWS + BM - 1) / BM, NCOLS / BN);
    gemm_qkvr_kernel<<<ggrid, 256, GEMM_SMEM>>>(
        x, Wq, bq, Wk, bk, Wv, bv, Wr, br);

    scatter_kernel<<<(NE + 255) / 256, 256>>>(edst);
    wesum_kernel<<<1, 512>>>(We);
    ebias_kernel<<<NE / 32, 256>>>(edata);
    logits_kernel<<<N_NODES * BATCH / 8, 256>>>(esrc);
    attn_kernel<<<N_NODES * BATCH * NH / 8, 256>>>(esrc, out);
}